// round 16
// baseline (speedup 1.0000x reference)
#include <cuda_runtime.h>
#include <cuda_fp16.h>
#include <math.h>
#include <stdint.h>

#define BB 2
#define SS 2048
#define DD 1024
#define HH 16
#define DHH 64
#define NQ (BB * SS * DD)
#define NW (DD * DD)

// Scratch (allocation-free), fp16
__device__ __half g_qh[NQ];   // head-major q [B,H,S,DH]
__device__ __half g_kh[NQ];   // head-major k
__device__ __half g_vh[NQ];   // head-major v
__device__ __half g_att[NQ];  // attention out, natural [B,S,D]
__device__ __half g_qr[NQ];   // converted inputs
__device__ __half g_kr[NQ];
__device__ __half g_vr[NQ];
__device__ __half g_wq[NW];   // converted weights
__device__ __half g_wk[NW];
__device__ __half g_wv[NW];
__device__ __half g_wo[NW];

// ---------------------------------------------------------------------------
__device__ __forceinline__ uint32_t h2u(__half2 h) {
    return *reinterpret_cast<uint32_t*>(&h);
}

__device__ __forceinline__ void mma_f16(float* c, const uint32_t* a,
                                        const uint32_t* b) {
    asm volatile(
        "mma.sync.aligned.m16n8k16.row.col.f32.f16.f16.f32 "
        "{%0,%1,%2,%3}, {%4,%5,%6,%7}, {%8,%9}, {%0,%1,%2,%3};\n"
        : "+f"(c[0]), "+f"(c[1]), "+f"(c[2]), "+f"(c[3])
        : "r"(a[0]), "r"(a[1]), "r"(a[2]), "r"(a[3]), "r"(b[0]), "r"(b[1]));
}

__device__ __forceinline__ void ldx4(uint32_t& r0, uint32_t& r1, uint32_t& r2,
                                     uint32_t& r3, uint32_t saddr) {
    asm volatile(
        "ldmatrix.sync.aligned.m8n8.x4.shared.b16 {%0,%1,%2,%3}, [%4];\n"
        : "=r"(r0), "=r"(r1), "=r"(r2), "=r"(r3)
        : "r"(saddr));
}

__device__ __forceinline__ void ldx4t(uint32_t& r0, uint32_t& r1, uint32_t& r2,
                                      uint32_t& r3, uint32_t saddr) {
    asm volatile(
        "ldmatrix.sync.aligned.m8n8.x4.trans.shared.b16 {%0,%1,%2,%3}, [%4];\n"
        : "=r"(r0), "=r"(r1), "=r"(r2), "=r"(r3)
        : "r"(saddr));
}

__device__ __forceinline__ void cp16(void* sdst, const void* gsrc) {
    uint32_t a = (uint32_t)__cvta_generic_to_shared(sdst);
    asm volatile("cp.async.cg.shared.global [%0], [%1], 16;" ::"r"(a),
                     "l"(gsrc));
}
#define CP_COMMIT() asm volatile("cp.async.commit_group;")
#define CP_WAIT0() asm volatile("cp.async.wait_group 0;" ::: "memory")

// ---------------------------------------------------------------------------
// Convert all GEMM operands to fp16. z selects tensor.
// ---------------------------------------------------------------------------
__global__ void convert_kernel(const float* __restrict__ Q,
                               const float* __restrict__ K,
                               const float* __restrict__ V,
                               const float* __restrict__ Wq,
                               const float* __restrict__ Wk,
                               const float* __restrict__ Wv,
                               const float* __restrict__ Wo) {
    const int z = blockIdx.z;
    const float* src;
    __half* dst;
    int n4;
    switch (z) {
        case 0: src = Q;  dst = g_qr; n4 = NQ / 4; break;
        case 1: src = K;  dst = g_kr; n4 = NQ / 4; break;
        case 2: src = V;  dst = g_vr; n4 = NQ / 4; break;
        case 3: src = Wq; dst = g_wq; n4 = NW / 4; break;
        case 4: src = Wk; dst = g_wk; n4 = NW / 4; break;
        case 5: src = Wv; dst = g_wv; n4 = NW / 4; break;
        default: src = Wo; dst = g_wo; n4 = NW / 4; break;
    }
    const int stride = gridDim.x * blockDim.x;
    for (int i = blockIdx.x * blockDim.x + threadIdx.x; i < n4; i += stride) {
        float4 v = ((const float4*)src)[i];
        uint2 u;
        u.x = h2u(__floats2half2_rn(v.x, v.y));
        u.y = h2u(__floats2half2_rn(v.z, v.w));
        ((uint2*)dst)[i] = u;
    }
}

// ---------------------------------------------------------------------------
// FP16 GEMM: C[m][n] = sum_k A[m][k]*W[n][k] + bias[n]
// m16n8k16, block 128x128x64, 256 threads / 8 warps, warp tile 64x32,
// cp.async 2-stage, all fragments via ldmatrix.x4.
// MODE 0: head-major half out (q/k/v). MODE 2: natural float out (final).
// ---------------------------------------------------------------------------
#define GST 36
#define GSTAGE (2 * 128 * GST)  // uint32 words per stage (A + W)

template <int MODE>
__device__ __forceinline__ void gemm_tc(const __half* __restrict__ A,
                                        const __half* __restrict__ W,
                                        const float* __restrict__ bias,
                                        void* __restrict__ outv) {
    extern __shared__ uint32_t sm[];
    const int t = threadIdx.x;  // 256 threads
    const int lane = t & 31, warp = t >> 5;
    const int wm = (warp >> 2) * 64;  // 2 row groups
    const int wn = (warp & 3) * 32;   // 4 col groups
    const int g = lane >> 2, tg = lane & 3;
    const int m0 = blockIdx.y * 128, n0 = blockIdx.x * 128;
    const int lr = t >> 3, lc = t & 7;  // 32 rows x 8 segs of 16B

    const int aRow = lane & 15;
    const int aOff = (lane >> 4) << 2;
    const int bRow = (lane & 7) + ((lane & 16) >> 1);
    const int bOff = (lane & 8) >> 1;

    float acc[4][4][4];
#pragma unroll
    for (int mt = 0; mt < 4; mt++)
#pragma unroll
        for (int nt = 0; nt < 4; nt++)
#pragma unroll
            for (int i = 0; i < 4; i++) acc[mt][nt][i] = 0.f;

    auto stage = [&](int buf, int k0) {
        uint32_t* As = sm + buf * GSTAGE;
        uint32_t* Ws = As + 128 * GST;
#pragma unroll
        for (int it = 0; it < 4; it++) {
            int r = lr + it * 32;
            cp16(&As[r * GST + lc * 4], &A[(size_t)(m0 + r) * DD + k0 + lc * 8]);
            cp16(&Ws[r * GST + lc * 4], &W[(size_t)(n0 + r) * DD + k0 + lc * 8]);
        }
        CP_COMMIT();
    };

    stage(0, 0);

    const uint32_t smBase = (uint32_t)__cvta_generic_to_shared(sm);

    for (int it = 0; it < DD / 64; it++) {
        const int buf = it & 1;
        CP_WAIT0();
        __syncthreads();
        if (it + 1 < DD / 64) stage(buf ^ 1, (it + 1) * 64);

        const uint32_t asB = smBase + buf * (GSTAGE * 4);
        const uint32_t wsB = asB + 128 * GST * 4;
#pragma unroll
        for (int ks = 0; ks < 4; ks++) {
            const int kk = ks * 8;
            uint32_t a[4][4], b[4][2];
#pragma unroll
            for (int mt = 0; mt < 4; mt++) {
                ldx4(a[mt][0], a[mt][1], a[mt][2], a[mt][3],
                     asB + 4 * ((wm + mt * 16 + aRow) * GST + kk + aOff));
            }
#pragma unroll
            for (int np = 0; np < 2; np++) {
                ldx4(b[np * 2][0], b[np * 2][1], b[np * 2 + 1][0],
                     b[np * 2 + 1][1],
                     wsB + 4 * ((wn + np * 16 + bRow) * GST + kk + bOff));
            }
#pragma unroll
            for (int mt = 0; mt < 4; mt++)
#pragma unroll
                for (int nt = 0; nt < 4; nt++)
                    mma_f16(acc[mt][nt], a[mt], b[nt]);
        }
        __syncthreads();
    }

#pragma unroll
    for (int mt = 0; mt < 4; mt++) {
#pragma unroll
        for (int i = 0; i < 2; i++) {
            int m = m0 + wm + mt * 16 + g + i * 8;
            int bI = m >> 11, s = m & (SS - 1);
#pragma unroll
            for (int nt = 0; nt < 4; nt++) {
                int n = n0 + wn + nt * 8 + tg * 2;
                float vx = acc[mt][nt][i * 2 + 0] + bias[n];
                float vy = acc[mt][nt][i * 2 + 1] + bias[n + 1];
                if (MODE == 0) {
                    int h = n >> 6, dh = n & 63;
                    uint32_t* out = (uint32_t*)outv;
                    out[(((size_t)(bI * HH + h) * SS + s) << 5) + (dh >> 1)] =
                        h2u(__floats2half2_rn(vx, vy));
                } else {
                    float* out = (float*)outv;
                    *(float2*)&out[(size_t)m * DD + n] = make_float2(vx, vy);
                }
            }
        }
    }
}

__global__ void __launch_bounds__(256, 2) proj_kernel(
    const float* __restrict__ bq, const float* __restrict__ bk,
    const float* __restrict__ bv) {
    int z = blockIdx.z;
    if (z == 2) {
        gemm_tc<0>(g_vr, g_wv, bv, g_vh);
    } else if (z == 1) {
        gemm_tc<0>(g_kr, g_wk, bk, g_kh);
    } else {
        gemm_tc<0>(g_qr, g_wq, bq, g_qh);
    }
}

__global__ void __launch_bounds__(256, 2) oproj_kernel(
    const float* __restrict__ bo, float* __restrict__ out) {
    gemm_tc<2>(g_att, g_wo, bo, out);
}

// ---------------------------------------------------------------------------
// FP16 mma.sync flash attention: 128 queries per CTA, 8 warps, 64-key tiles
// (the proven R12 per-warp shape; only more warps share each K/V staging).
// cp.async double-buffered K/V, natural [key][d]. QK K-frags + PV P-frags
// via ldmatrix.x4; PV V-frags via ldmatrix.x4.trans. Universal causal test.
// Descending-qb schedule. smem 55 KB -> 2 CTAs/SM -> 16 warps/SM.
// ---------------------------------------------------------------------------
#define AST 36
#define OFF_K0 0
#define OFF_K1 (64 * AST)
#define OFF_V0 (2 * 64 * AST)
#define OFF_V1 (3 * 64 * AST)
#define OFF_P (4 * 64 * AST)
#define ATT_SMEM ((4 * 64 * AST + 128 * AST) * 4)

__global__ void __launch_bounds__(256, 2) attn_kernel(const int* __restrict__ mask) {
    extern __shared__ uint32_t smu[];
    const int t = threadIdx.x;  // 256 threads
    const int lane = t & 31, w = t >> 5;  // 8 warps
    const int g = lane >> 2, tg = lane & 3;
    const int qb = (gridDim.x - 1) - blockIdx.x;  // heavy blocks first
    const int bh = blockIdx.y;
    const int b = bh >> 4, h = bh & 15;
    const size_t base = (size_t)bh * SS * DHH;
    const __half* Qp = g_qh + base;
    const __half* Kp = g_kh + base;
    const __half* Vp = g_vh + base;

    const int lr = t >> 3, lc = t & 7;  // 32 rows x 8 segs of 16B
    const int aRow = lane & 15;
    const int aOff = (lane >> 4) << 2;
    const int bRow = (lane & 7) + ((lane & 16) >> 1);
    const int bOff = (lane & 8) >> 1;

    auto stageKV = [&](int buf, int kb) {
        uint32_t* sK = smu + (buf ? OFF_K1 : OFF_K0);
        uint32_t* sV = smu + (buf ? OFF_V1 : OFF_V0);
#pragma unroll
        for (int i = 0; i < 2; i++) {
            int r = lr + i * 32;
            cp16(&sK[r * AST + lc * 4], &Kp[(size_t)(kb * 64 + r) * 64 + lc * 8]);
            cp16(&sV[r * AST + lc * 4], &Vp[(size_t)(kb * 64 + r) * 64 + lc * 8]);
        }
        CP_COMMIT();
    };
    stageKV(0, 0);

    const uint32_t smuBase = (uint32_t)__cvta_generic_to_shared(smu);
    const uint32_t pBase = smuBase + OFF_P * 4;

    // Stage 128 Q rows through sP, pull warp A-fragments via ldmatrix
    uint32_t* sP = smu + OFF_P;
#pragma unroll
    for (int i = 0; i < 4; i++) {
        int r = lr + i * 32;
        *(float4*)&sP[r * AST + lc * 4] =
            *(const float4*)&Qp[(size_t)(qb * 128 + r) * 64 + lc * 8];
    }
    __syncthreads();
    uint32_t aq[4][4];
#pragma unroll
    for (int ks = 0; ks < 4; ks++) {
        ldx4(aq[ks][0], aq[ks][1], aq[ks][2], aq[ks][3],
             pBase + 4 * ((w * 16 + aRow) * AST + ks * 8 + aOff));
    }
    __syncthreads();  // done reading Q before P overwrites

    float m0 = -INFINITY, m1 = -INFINITY, l0 = 0.f, l1 = 0.f;
    float o[8][4];
#pragma unroll
    for (int nt = 0; nt < 8; nt++)
#pragma unroll
        for (int i = 0; i < 4; i++) o[nt][i] = 0.f;

    const float scale = 0.125f;  // 1/sqrt(64)
    const int row0g = qb * 128 + w * 16 + g;
    const int r0 = (w * 16 + g) * AST, r1 = (w * 16 + g + 8) * AST;
    const int nkb = 2 * qb + 2;

    for (int kb = 0; kb < nkb; kb++) {
        const int buf = kb & 1;
        CP_WAIT0();
        __syncthreads();
        if (kb + 1 < nkb) stageKV(buf ^ 1, kb + 1);

        const uint32_t kB = smuBase + (buf ? OFF_K1 : OFF_K0) * 4;
        const uint32_t vB = smuBase + (buf ? OFF_V1 : OFF_V0) * 4;

        // QK^T: 4 slices of d=16, 8 mma each
        float c_[8][4];
#pragma unroll
        for (int nt = 0; nt < 8; nt++)
#pragma unroll
            for (int i = 0; i < 4; i++) c_[nt][i] = 0.f;
#pragma unroll
        for (int ks = 0; ks < 4; ks++) {
            const int kk = ks * 8;
            uint32_t bf[8][2];
#pragma unroll
            for (int np = 0; np < 4; np++) {
                ldx4(bf[np * 2][0], bf[np * 2][1], bf[np * 2 + 1][0],
                     bf[np * 2 + 1][1],
                     kB + 4 * ((np * 16 + bRow) * AST + kk + bOff));
            }
#pragma unroll
            for (int nt = 0; nt < 8; nt++) mma_f16(c_[nt], aq[ks], bf[nt]);
        }

        // Scale + padding + universal causal mask (col > row)
        const int colb = kb * 64 + tg * 2;
#pragma unroll
        for (int nt = 0; nt < 8; nt++) {
            int col = colb + nt * 8;
            int mk0 = __ldg(&mask[b * SS + col]);
            int mk1 = __ldg(&mask[b * SS + col + 1]);
#pragma unroll
            for (int hh = 0; hh < 2; hh++) {
                int row = row0g + hh * 8;
                float v0 = c_[nt][hh * 2] * scale;
                float v1 = c_[nt][hh * 2 + 1] * scale;
                if (mk0 == 0 || col > row) v0 = -INFINITY;
                if (mk1 == 0 || col + 1 > row) v1 = -INFINITY;
                c_[nt][hh * 2] = v0;
                c_[nt][hh * 2 + 1] = v1;
            }
        }

        // Online softmax per row half (rows g, g+8)
#pragma unroll
        for (int hh = 0; hh < 2; hh++) {
            float mprev = hh ? m1 : m0;
            float rm = -INFINITY;
#pragma unroll
            for (int nt = 0; nt < 8; nt++)
                rm = fmaxf(rm, fmaxf(c_[nt][hh * 2], c_[nt][hh * 2 + 1]));
            rm = fmaxf(rm, __shfl_xor_sync(0xffffffffu, rm, 1));
            rm = fmaxf(rm, __shfl_xor_sync(0xffffffffu, rm, 2));
            float mn = fmaxf(mprev, rm);
            float scl = __expf(mprev - mn);
            float ps = 0.f;
#pragma unroll
            for (int nt = 0; nt < 8; nt++) {
                float p0 = __expf(c_[nt][hh * 2] - mn);
                float p1 = __expf(c_[nt][hh * 2 + 1] - mn);
                c_[nt][hh * 2] = p0;
                c_[nt][hh * 2 + 1] = p1;
                ps += p0 + p1;
            }
            ps += __shfl_xor_sync(0xffffffffu, ps, 1);
            ps += __shfl_xor_sync(0xffffffffu, ps, 2);
            if (hh) {
                l1 = l1 * scl + ps;
                m1 = mn;
            } else {
                l0 = l0 * scl + ps;
                m0 = mn;
            }
#pragma unroll
            for (int nt = 0; nt < 8; nt++) {
                o[nt][hh * 2] *= scl;
                o[nt][hh * 2 + 1] *= scl;
            }
        }

        // Store P as half2 into warp-private sP rows
#pragma unroll
        for (int nt = 0; nt < 8; nt++) {
            sP[r0 + nt * 4 + tg] = h2u(__floats2half2_rn(c_[nt][0], c_[nt][1]));
            sP[r1 + nt * 4 + tg] = h2u(__floats2half2_rn(c_[nt][2], c_[nt][3]));
        }
        __syncwarp();

        // P * V: P A-frags via ldmatrix.x4; V B-frags via ldmatrix.x4.trans
#pragma unroll
        for (int ks = 0; ks < 4; ks++) {
            uint32_t ap[4];
            ldx4(ap[0], ap[1], ap[2], ap[3],
                 pBase + 4 * ((w * 16 + aRow) * AST + ks * 8 + aOff));
            uint32_t vRow = vB + 4 * ((ks * 16 + (lane & 15)) * AST) +
                            ((lane >> 4) << 4);
#pragma unroll
            for (int np = 0; np < 4; np++) {
                uint32_t bv0[2], bv1[2];
                ldx4t(bv0[0], bv0[1], bv1[0], bv1[1], vRow + np * 32);
                mma_f16(o[np * 2], ap, bv0);
                mma_f16(o[np * 2 + 1], ap, bv1);
            }
        }
    }

    // Epilogue: normalize + half2 store to g_att natural [B,S,D]
    float inv0 = 1.f / l0, inv1 = 1.f / l1;
    uint32_t* outw = (uint32_t*)g_att;
#pragma unroll
    for (int nt = 0; nt < 8; nt++) {
        int dw = h * 32 + nt * 4 + tg;  // half2 word within D row
        outw[(size_t)(b * SS + row0g) * (DD / 2) + dw] =
            h2u(__floats2half2_rn(o[nt][0] * inv0, o[nt][1] * inv0));
        outw[(size_t)(b * SS + row0g + 8) * (DD / 2) + dw] =
            h2u(__floats2half2_rn(o[nt][2] * inv1, o[nt][3] * inv1));
    }
}

// ---------------------------------------------------------------------------
extern "C" void kernel_launch(void* const* d_in, const int* in_sizes, int n_in,
                              void* d_out, int out_size) {
    const float* Q = (const float*)d_in[0];
    const float* K = (const float*)d_in[1];
    const float* V = (const float*)d_in[2];
    const int* mask = (const int*)d_in[3];
    const float* Wq = (const float*)d_in[4];
    const float* bq = (const float*)d_in[5];
    const float* Wk = (const float*)d_in[6];
    const float* bk = (const float*)d_in[7];
    const float* Wv = (const float*)d_in[8];
    const float* bv = (const float*)d_in[9];
    const float* Wo = (const float*)d_in[10];
    const float* bo = (const float*)d_in[11];
    float* out = (float*)d_out;

    const int gemm_smem = 2 * GSTAGE * (int)sizeof(uint32_t);  // 73728 B
    static int configured = 0;
    if (!configured) {
        cudaFuncSetAttribute(proj_kernel, cudaFuncAttributeMaxDynamicSharedMemorySize,
                             gemm_smem);
        cudaFuncSetAttribute(oproj_kernel, cudaFuncAttributeMaxDynamicSharedMemorySize,
                             gemm_smem);
        cudaFuncSetAttribute(attn_kernel, cudaFuncAttributeMaxDynamicSharedMemorySize,
                             ATT_SMEM);
        configured = 1;
    }

    // Convert all GEMM operands to fp16
    dim3 gconv(512, 1, 7);
    convert_kernel<<<gconv, 256>>>(Q, K, V, Wq, Wk, Wv, Wo);

    dim3 gproj(DD / 128, (BB * SS) / 128, 3);
    proj_kernel<<<gproj, 256, gemm_smem>>>(bq, bk, bv);

    dim3 gattn(SS / 128, BB * HH);
    attn_kernel<<<gattn, 256, ATT_SMEM>>>(mask);

    dim3 gout(DD / 128, (BB * SS) / 128);
    oproj_kernel<<<gout, 256, gemm_smem>>>(bo, out);
}

// round 17
// speedup vs baseline: 1.0878x; 1.0878x over previous
#include <cuda_runtime.h>
#include <cuda_fp16.h>
#include <math.h>
#include <stdint.h>

#define BB 2
#define SS 2048
#define DD 1024
#define HH 16
#define DHH 64
#define NQ (BB * SS * DD)
#define NW (DD * DD)

// Scratch (allocation-free), fp16
__device__ __half g_qh[NQ];   // head-major q [B,H,S,DH]
__device__ __half g_kh[NQ];   // head-major k
__device__ __half g_vh[NQ];   // head-major v
__device__ __half g_att[NQ];  // attention out, natural [B,S,D]
__device__ __half g_qr[NQ];   // converted inputs
__device__ __half g_kr[NQ];
__device__ __half g_vr[NQ];
__device__ __half g_wq[NW];   // converted weights
__device__ __half g_wk[NW];
__device__ __half g_wv[NW];
__device__ __half g_wo[NW];

// ---------------------------------------------------------------------------
__device__ __forceinline__ uint32_t h2u(__half2 h) {
    return *reinterpret_cast<uint32_t*>(&h);
}

__device__ __forceinline__ void mma_f16(float* c, const uint32_t* a,
                                        const uint32_t* b) {
    asm volatile(
        "mma.sync.aligned.m16n8k16.row.col.f32.f16.f16.f32 "
        "{%0,%1,%2,%3}, {%4,%5,%6,%7}, {%8,%9}, {%0,%1,%2,%3};\n"
        : "+f"(c[0]), "+f"(c[1]), "+f"(c[2]), "+f"(c[3])
        : "r"(a[0]), "r"(a[1]), "r"(a[2]), "r"(a[3]), "r"(b[0]), "r"(b[1]));
}

__device__ __forceinline__ void ldx4(uint32_t& r0, uint32_t& r1, uint32_t& r2,
                                     uint32_t& r3, uint32_t saddr) {
    asm volatile(
        "ldmatrix.sync.aligned.m8n8.x4.shared.b16 {%0,%1,%2,%3}, [%4];\n"
        : "=r"(r0), "=r"(r1), "=r"(r2), "=r"(r3)
        : "r"(saddr));
}

__device__ __forceinline__ void ldx4t(uint32_t& r0, uint32_t& r1, uint32_t& r2,
                                      uint32_t& r3, uint32_t saddr) {
    asm volatile(
        "ldmatrix.sync.aligned.m8n8.x4.trans.shared.b16 {%0,%1,%2,%3}, [%4];\n"
        : "=r"(r0), "=r"(r1), "=r"(r2), "=r"(r3)
        : "r"(saddr));
}

__device__ __forceinline__ void cp16(void* sdst, const void* gsrc) {
    uint32_t a = (uint32_t)__cvta_generic_to_shared(sdst);
    asm volatile("cp.async.cg.shared.global [%0], [%1], 16;" ::"r"(a),
                     "l"(gsrc));
}
#define CP_COMMIT() asm volatile("cp.async.commit_group;")
#define CP_WAIT0() asm volatile("cp.async.wait_group 0;" ::: "memory")

// ---------------------------------------------------------------------------
// Convert all GEMM operands to fp16. z selects tensor.
// ---------------------------------------------------------------------------
__global__ void convert_kernel(const float* __restrict__ Q,
                               const float* __restrict__ K,
                               const float* __restrict__ V,
                               const float* __restrict__ Wq,
                               const float* __restrict__ Wk,
                               const float* __restrict__ Wv,
                               const float* __restrict__ Wo) {
    const int z = blockIdx.z;
    const float* src;
    __half* dst;
    int n4;
    switch (z) {
        case 0: src = Q;  dst = g_qr; n4 = NQ / 4; break;
        case 1: src = K;  dst = g_kr; n4 = NQ / 4; break;
        case 2: src = V;  dst = g_vr; n4 = NQ / 4; break;
        case 3: src = Wq; dst = g_wq; n4 = NW / 4; break;
        case 4: src = Wk; dst = g_wk; n4 = NW / 4; break;
        case 5: src = Wv; dst = g_wv; n4 = NW / 4; break;
        default: src = Wo; dst = g_wo; n4 = NW / 4; break;
    }
    const int stride = gridDim.x * blockDim.x;
    for (int i = blockIdx.x * blockDim.x + threadIdx.x; i < n4; i += stride) {
        float4 v = ((const float4*)src)[i];
        uint2 u;
        u.x = h2u(__floats2half2_rn(v.x, v.y));
        u.y = h2u(__floats2half2_rn(v.z, v.w));
        ((uint2*)dst)[i] = u;
    }
}

// ---------------------------------------------------------------------------
// FP16 GEMM: C[m][n] = sum_k A[m][k]*W[n][k] + bias[n]
// m16n8k16, block 128x128x64, 256 threads / 8 warps, warp tile 64x32,
// cp.async 2-stage, all fragments via ldmatrix.x4.
// MODE 0: head-major half out (q/k/v). MODE 2: natural float out (final).
// ---------------------------------------------------------------------------
#define GST 36
#define GSTAGE (2 * 128 * GST)  // uint32 words per stage (A + W)

template <int MODE>
__device__ __forceinline__ void gemm_tc(const __half* __restrict__ A,
                                        const __half* __restrict__ W,
                                        const float* __restrict__ bias,
                                        void* __restrict__ outv) {
    extern __shared__ uint32_t sm[];
    const int t = threadIdx.x;  // 256 threads
    const int lane = t & 31, warp = t >> 5;
    const int wm = (warp >> 2) * 64;  // 2 row groups
    const int wn = (warp & 3) * 32;   // 4 col groups
    const int g = lane >> 2, tg = lane & 3;
    const int m0 = blockIdx.y * 128, n0 = blockIdx.x * 128;
    const int lr = t >> 3, lc = t & 7;  // 32 rows x 8 segs of 16B

    const int aRow = lane & 15;
    const int aOff = (lane >> 4) << 2;
    const int bRow = (lane & 7) + ((lane & 16) >> 1);
    const int bOff = (lane & 8) >> 1;

    float acc[4][4][4];
#pragma unroll
    for (int mt = 0; mt < 4; mt++)
#pragma unroll
        for (int nt = 0; nt < 4; nt++)
#pragma unroll
            for (int i = 0; i < 4; i++) acc[mt][nt][i] = 0.f;

    auto stage = [&](int buf, int k0) {
        uint32_t* As = sm + buf * GSTAGE;
        uint32_t* Ws = As + 128 * GST;
#pragma unroll
        for (int it = 0; it < 4; it++) {
            int r = lr + it * 32;
            cp16(&As[r * GST + lc * 4], &A[(size_t)(m0 + r) * DD + k0 + lc * 8]);
            cp16(&Ws[r * GST + lc * 4], &W[(size_t)(n0 + r) * DD + k0 + lc * 8]);
        }
        CP_COMMIT();
    };

    stage(0, 0);

    const uint32_t smBase = (uint32_t)__cvta_generic_to_shared(sm);

    for (int it = 0; it < DD / 64; it++) {
        const int buf = it & 1;
        CP_WAIT0();
        __syncthreads();
        if (it + 1 < DD / 64) stage(buf ^ 1, (it + 1) * 64);

        const uint32_t asB = smBase + buf * (GSTAGE * 4);
        const uint32_t wsB = asB + 128 * GST * 4;
#pragma unroll
        for (int ks = 0; ks < 4; ks++) {
            const int kk = ks * 8;
            uint32_t a[4][4], b[4][2];
#pragma unroll
            for (int mt = 0; mt < 4; mt++) {
                ldx4(a[mt][0], a[mt][1], a[mt][2], a[mt][3],
                     asB + 4 * ((wm + mt * 16 + aRow) * GST + kk + aOff));
            }
#pragma unroll
            for (int np = 0; np < 2; np++) {
                ldx4(b[np * 2][0], b[np * 2][1], b[np * 2 + 1][0],
                     b[np * 2 + 1][1],
                     wsB + 4 * ((wn + np * 16 + bRow) * GST + kk + bOff));
            }
#pragma unroll
            for (int mt = 0; mt < 4; mt++)
#pragma unroll
                for (int nt = 0; nt < 4; nt++)
                    mma_f16(acc[mt][nt], a[mt], b[nt]);
        }
        __syncthreads();
    }

#pragma unroll
    for (int mt = 0; mt < 4; mt++) {
#pragma unroll
        for (int i = 0; i < 2; i++) {
            int m = m0 + wm + mt * 16 + g + i * 8;
            int bI = m >> 11, s = m & (SS - 1);
#pragma unroll
            for (int nt = 0; nt < 4; nt++) {
                int n = n0 + wn + nt * 8 + tg * 2;
                float vx = acc[mt][nt][i * 2 + 0] + bias[n];
                float vy = acc[mt][nt][i * 2 + 1] + bias[n + 1];
                if (MODE == 0) {
                    int h = n >> 6, dh = n & 63;
                    uint32_t* out = (uint32_t*)outv;
                    out[(((size_t)(bI * HH + h) * SS + s) << 5) + (dh >> 1)] =
                        h2u(__floats2half2_rn(vx, vy));
                } else {
                    float* out = (float*)outv;
                    *(float2*)&out[(size_t)m * DD + n] = make_float2(vx, vy);
                }
            }
        }
    }
}

__global__ void __launch_bounds__(256, 2) proj_kernel(
    const float* __restrict__ bq, const float* __restrict__ bk,
    const float* __restrict__ bv) {
    int z = blockIdx.z;
    if (z == 2) {
        gemm_tc<0>(g_vr, g_wv, bv, g_vh);
    } else if (z == 1) {
        gemm_tc<0>(g_kr, g_wk, bk, g_kh);
    } else {
        gemm_tc<0>(g_qr, g_wq, bq, g_qh);
    }
}

__global__ void __launch_bounds__(256, 2) oproj_kernel(
    const float* __restrict__ bo, float* __restrict__ out) {
    gemm_tc<2>(g_att, g_wo, bo, out);
}

// ---------------------------------------------------------------------------
// FP16 mma.sync flash attention (R12 shape, exp2-domain softmax).
// Grid (S/64, B*H), 128 threads (4 warps), warp w owns 16 query rows.
// cp.async double-buffered K/V, natural [key][d]. QK K-frags + PV P-frags
// via ldmatrix.x4; PV V-frags via ldmatrix.x4.trans. Descending-qb order.
// ---------------------------------------------------------------------------
#define AST 36
#define OFF_K0 0
#define OFF_K1 (64 * AST)
#define OFF_V0 (2 * 64 * AST)
#define OFF_V1 (3 * 64 * AST)
#define OFF_P (4 * 64 * AST)
#define ATT_SMEM (5 * 64 * AST * 4)

__global__ void __launch_bounds__(128) attn_kernel(const int* __restrict__ mask) {
    extern __shared__ uint32_t smu[];
    const int t = threadIdx.x;
    const int lane = t & 31, w = t >> 5;
    const int g = lane >> 2, tg = lane & 3;
    const int qb = (gridDim.x - 1) - blockIdx.x;
    const int bh = blockIdx.y;
    const int b = bh >> 4, h = bh & 15;
    const size_t base = (size_t)bh * SS * DHH;
    const __half* Qp = g_qh + base;
    const __half* Kp = g_kh + base;
    const __half* Vp = g_vh + base;
    const int* maskb = mask + b * SS;

    const int lr = t >> 3, lc = t & 7;
    const int aRow = lane & 15;
    const int aOff = (lane >> 4) << 2;
    const int bRow = (lane & 7) + ((lane & 16) >> 1);
    const int bOff = (lane & 8) >> 1;

    auto stageKV = [&](int buf, int kb) {
        uint32_t* sK = smu + (buf ? OFF_K1 : OFF_K0);
        uint32_t* sV = smu + (buf ? OFF_V1 : OFF_V0);
#pragma unroll
        for (int i = 0; i < 4; i++) {
            int r = lr + i * 16;
            cp16(&sK[r * AST + lc * 4], &Kp[(size_t)(kb * 64 + r) * 64 + lc * 8]);
            cp16(&sV[r * AST + lc * 4], &Vp[(size_t)(kb * 64 + r) * 64 + lc * 8]);
        }
        CP_COMMIT();
    };
    stageKV(0, 0);

    const uint32_t smuBase = (uint32_t)__cvta_generic_to_shared(smu);
    const uint32_t pBase = smuBase + OFF_P * 4;

    uint32_t* sP = smu + OFF_P;
#pragma unroll
    for (int i = 0; i < 4; i++) {
        int r = lr + i * 16;
        *(float4*)&sP[r * AST + lc * 4] =
            *(const float4*)&Qp[(size_t)(qb * 64 + r) * 64 + lc * 8];
    }
    __syncthreads();
    uint32_t aq[4][4];
#pragma unroll
    for (int ks = 0; ks < 4; ks++) {
        ldx4(aq[ks][0], aq[ks][1], aq[ks][2], aq[ks][3],
             pBase + 4 * ((w * 16 + aRow) * AST + ks * 8 + aOff));
    }
    __syncthreads();

    float m0 = -INFINITY, m1 = -INFINITY, l0 = 0.f, l1 = 0.f;
    float o[8][4];
#pragma unroll
    for (int nt = 0; nt < 8; nt++)
#pragma unroll
        for (int i = 0; i < 4; i++) o[nt][i] = 0.f;

    // log2-domain scale: 1/sqrt(64) * log2(e)
    const float scale2 = 0.125f * 1.4426950408889634f;
    const int row0g = qb * 64 + w * 16 + g;
    const int r0 = (w * 16 + g) * AST, r1 = (w * 16 + g + 8) * AST;

    for (int kb = 0; kb <= qb; kb++) {
        const int buf = kb & 1;
        CP_WAIT0();
        __syncthreads();
        if (kb < qb) stageKV(buf ^ 1, kb + 1);

        const uint32_t kB = smuBase + (buf ? OFF_K1 : OFF_K0) * 4;
        const uint32_t vB = smuBase + (buf ? OFF_V1 : OFF_V0) * 4;

        float c_[8][4];
#pragma unroll
        for (int nt = 0; nt < 8; nt++)
#pragma unroll
            for (int i = 0; i < 4; i++) c_[nt][i] = 0.f;
#pragma unroll
        for (int ks = 0; ks < 4; ks++) {
            const int kk = ks * 8;
            uint32_t bf[8][2];
#pragma unroll
            for (int np = 0; np < 4; np++) {
                ldx4(bf[np * 2][0], bf[np * 2][1], bf[np * 2 + 1][0],
                     bf[np * 2 + 1][1],
                     kB + 4 * ((np * 16 + bRow) * AST + kk + bOff));
            }
#pragma unroll
            for (int nt = 0; nt < 8; nt++) mma_f16(c_[nt], aq[ks], bf[nt]);
        }

        const int colb = kb * 64 + tg * 2;
#pragma unroll
        for (int nt = 0; nt < 8; nt++) {
            int col = colb + nt * 8;
            int mk0 = __ldg(&maskb[col]);
            int mk1 = __ldg(&maskb[col + 1]);
#pragma unroll
            for (int hh = 0; hh < 2; hh++) {
                int row = row0g + hh * 8;
                float v0 = c_[nt][hh * 2] * scale2;
                float v1 = c_[nt][hh * 2 + 1] * scale2;
                if (mk0 == 0 || (kb == qb && col > row)) v0 = -INFINITY;
                if (mk1 == 0 || (kb == qb && col + 1 > row)) v1 = -INFINITY;
                c_[nt][hh * 2] = v0;
                c_[nt][hh * 2 + 1] = v1;
            }
        }

        // Online softmax in log2 domain (rows g, g+8)
#pragma unroll
        for (int hh = 0; hh < 2; hh++) {
            float mprev = hh ? m1 : m0;
            float rm = -INFINITY;
#pragma unroll
            for (int nt = 0; nt < 8; nt++)
                rm = fmaxf(rm, fmaxf(c_[nt][hh * 2], c_[nt][hh * 2 + 1]));
            rm = fmaxf(rm, __shfl_xor_sync(0xffffffffu, rm, 1));
            rm = fmaxf(rm, __shfl_xor_sync(0xffffffffu, rm, 2));
            float mn = fmaxf(mprev, rm);
            float scl = exp2f(mprev - mn);
            float ps = 0.f;
#pragma unroll
            for (int nt = 0; nt < 8; nt++) {
                float p0 = exp2f(c_[nt][hh * 2] - mn);
                float p1 = exp2f(c_[nt][hh * 2 + 1] - mn);
                c_[nt][hh * 2] = p0;
                c_[nt][hh * 2 + 1] = p1;
                ps += p0 + p1;
            }
            ps += __shfl_xor_sync(0xffffffffu, ps, 1);
            ps += __shfl_xor_sync(0xffffffffu, ps, 2);
            if (hh) {
                l1 = l1 * scl + ps;
                m1 = mn;
            } else {
                l0 = l0 * scl + ps;
                m0 = mn;
            }
#pragma unroll
            for (int nt = 0; nt < 8; nt++) {
                o[nt][hh * 2] *= scl;
                o[nt][hh * 2 + 1] *= scl;
            }
        }

#pragma unroll
        for (int nt = 0; nt < 8; nt++) {
            sP[r0 + nt * 4 + tg] = h2u(__floats2half2_rn(c_[nt][0], c_[nt][1]));
            sP[r1 + nt * 4 + tg] = h2u(__floats2half2_rn(c_[nt][2], c_[nt][3]));
        }
        __syncwarp();

#pragma unroll
        for (int ks = 0; ks < 4; ks++) {
            uint32_t ap[4];
            ldx4(ap[0], ap[1], ap[2], ap[3],
                 pBase + 4 * ((w * 16 + aRow) * AST + ks * 8 + aOff));
            uint32_t vRow = vB + 4 * ((ks * 16 + (lane & 15)) * AST) +
                            ((lane >> 4) << 4);
#pragma unroll
            for (int np = 0; np < 4; np++) {
                uint32_t bv0[2], bv1[2];
                ldx4t(bv0[0], bv0[1], bv1[0], bv1[1], vRow + np * 32);
                mma_f16(o[np * 2], ap, bv0);
                mma_f16(o[np * 2 + 1], ap, bv1);
            }
        }
    }

    float inv0 = 1.f / l0, inv1 = 1.f / l1;
    uint32_t* outw = (uint32_t*)g_att;
#pragma unroll
    for (int nt = 0; nt < 8; nt++) {
        int dw = h * 32 + nt * 4 + tg;
        outw[(size_t)(b * SS + row0g) * (DD / 2) + dw] =
            h2u(__floats2half2_rn(o[nt][0] * inv0, o[nt][1] * inv0));
        outw[(size_t)(b * SS + row0g + 8) * (DD / 2) + dw] =
            h2u(__floats2half2_rn(o[nt][2] * inv1, o[nt][3] * inv1));
    }
}

// ---------------------------------------------------------------------------
extern "C" void kernel_launch(void* const* d_in, const int* in_sizes, int n_in,
                              void* d_out, int out_size) {
    const float* Q = (const float*)d_in[0];
    const float* K = (const float*)d_in[1];
    const float* V = (const float*)d_in[2];
    const int* mask = (const int*)d_in[3];
    const float* Wq = (const float*)d_in[4];
    const float* bq = (const float*)d_in[5];
    const float* Wk = (const float*)d_in[6];
    const float* bk = (const float*)d_in[7];
    const float* Wv = (const float*)d_in[8];
    const float* bv = (const float*)d_in[9];
    const float* Wo = (const float*)d_in[10];
    const float* bo = (const float*)d_in[11];
    float* out = (float*)d_out;

    const int gemm_smem = 2 * GSTAGE * (int)sizeof(uint32_t);  // 73728 B
    static int configured = 0;
    if (!configured) {
        cudaFuncSetAttribute(proj_kernel, cudaFuncAttributeMaxDynamicSharedMemorySize,
                             gemm_smem);
        cudaFuncSetAttribute(oproj_kernel, cudaFuncAttributeMaxDynamicSharedMemorySize,
                             gemm_smem);
        cudaFuncSetAttribute(attn_kernel, cudaFuncAttributeMaxDynamicSharedMemorySize,
                             ATT_SMEM);
        configured = 1;
    }

    // Convert all GEMM operands to fp16
    dim3 gconv(512, 1, 7);
    convert_kernel<<<gconv, 256>>>(Q, K, V, Wq, Wk, Wv, Wo);

    dim3 gproj(DD / 128, (BB * SS) / 128, 3);
    proj_kernel<<<gproj, 256, gemm_smem>>>(bq, bk, bv);

    dim3 gattn(SS / 64, BB * HH);
    attn_kernel<<<gattn, 128, ATT_SMEM>>>(mask);

    dim3 gout(DD / 128, (BB * SS) / 128);
    oproj_kernel<<<gout, 256, gemm_smem>>>(bo, out);
}